// round 13
// baseline (speedup 1.0000x reference)
#include <cuda_runtime.h>

#define HID 768
#define NTOK 8
#define FSZ 32
#define BATCH 64

__device__ float g_t[BATCH * NTOK * HID];
__device__ float g_cwsum[NTOK];

__device__ __forceinline__ void st_cs_v4(float* p, float4 v) {
    asm volatile("st.global.cs.v4.f32 [%0], {%1,%2,%3,%4};"
                 :: "l"(p), "f"(v.x), "f"(v.y), "f"(v.z), "f"(v.w) : "memory");
}
__device__ __forceinline__ float4 ld_cs_v4(const float* p) {
    float4 v;
    asm volatile("ld.global.cs.v4.f32 {%0,%1,%2,%3}, [%4];"
                 : "=f"(v.x), "=f"(v.y), "=f"(v.z), "=f"(v.w) : "l"(p));
    return v;
}

// ---------------------------------------------------------------------------
// Kernel 1: t = LN2( Linear_over_tokens( LN1(token) ) ) + cwsum  (unchanged)
// ---------------------------------------------------------------------------
__global__ __launch_bounds__(256) void prep_kernel(
    const float* __restrict__ token,
    const float* __restrict__ ln1_w, const float* __restrict__ ln1_b,
    const float* __restrict__ lin_w, const float* __restrict__ lin_b,
    const float* __restrict__ ln2_w, const float* __restrict__ ln2_b,
    const float* __restrict__ conv_w)
{
    __shared__ float s[NTOK][HID];
    __shared__ float lw[NTOK * NTOK + NTOK];

    int b = blockIdx.x, tid = threadIdx.x, lane = tid & 31, w = tid >> 5;

    if (b == BATCH) {
        float sum = 0.f;
        for (int h = lane; h < HID; h += 32) sum += conv_w[w * HID + h];
        #pragma unroll
        for (int o = 16; o; o >>= 1) sum += __shfl_xor_sync(0xffffffffu, sum, o);
        if (lane == 0) g_cwsum[w] = sum;
        return;
    }

    if (tid < NTOK * NTOK) lw[tid] = lin_w[tid];
    if (tid < NTOK)        lw[NTOK * NTOK + tid] = lin_b[tid];
    for (int i = tid; i < NTOK * HID; i += 256)
        s[0][i] = token[(size_t)b * NTOK * HID + i];
    __syncthreads();

    {   // LN1
        float sum = 0.f, sq = 0.f;
        for (int h = lane; h < HID; h += 32) { float v = s[w][h]; sum += v; sq += v * v; }
        #pragma unroll
        for (int o = 16; o; o >>= 1) {
            sum += __shfl_xor_sync(0xffffffffu, sum, o);
            sq  += __shfl_xor_sync(0xffffffffu, sq,  o);
        }
        float mu = sum * (1.f / HID);
        float rs = rsqrtf(sq * (1.f / HID) - mu * mu + 1e-5f);
        for (int h = lane; h < HID; h += 32)
            s[w][h] = (s[w][h] - mu) * rs * ln1_w[h] + ln1_b[h];
    }
    __syncthreads();

    for (int h = tid; h < HID; h += 256) {   // Linear over tokens
        float v[NTOK];
        #pragma unroll
        for (int n = 0; n < NTOK; n++) v[n] = s[n][h];
        #pragma unroll
        for (int m = 0; m < NTOK; m++) {
            float a = lw[NTOK * NTOK + m];
            #pragma unroll
            for (int n = 0; n < NTOK; n++) a += lw[m * NTOK + n] * v[n];
            s[m][h] = a;
        }
    }
    __syncthreads();

    {   // LN2 -> g_t
        float sum = 0.f, sq = 0.f;
        for (int h = lane; h < HID; h += 32) { float v = s[w][h]; sum += v; sq += v * v; }
        #pragma unroll
        for (int o = 16; o; o >>= 1) {
            sum += __shfl_xor_sync(0xffffffffu, sum, o);
            sq  += __shfl_xor_sync(0xffffffffu, sq,  o);
        }
        float mu = sum * (1.f / HID);
        float rs = rsqrtf(sq * (1.f / HID) - mu * mu + 1e-5f);
        for (int h = lane; h < HID; h += 32)
            g_t[((size_t)b * NTOK + w) * HID + h] = (s[w][h] - mu) * rs * ln2_w[h] + ln2_b[h];
    }
}

// ---------------------------------------------------------------------------
// Kernel 2: 256 threads, 4 blocks/SM, ~35 KB smem. Register discipline:
//  acc[4][8] (GEMM) and tv[8] (output) must NEVER be co-live — tv is loaded
//  only after phase F's barrier, once acc is dead. Keeps regs <= 64 unspilled.
// ---------------------------------------------------------------------------
#define PSTRIDE 9
#define OFF_WP   0                            // [8][768]
#define OFF_PART (OFF_WP + 8 * HID)           // [256][9]  (also c0 staging [48])
#define OFF_MIX  (OFF_PART + 256 * PSTRIDE)   // [8][32]
#define OFF_C0   (OFF_MIX + 256)              // [8]
#define OFF_CWS  (OFF_C0 + 8)                 // [8]
#define OFF_LNW  (OFF_CWS + 8)                // [32]
#define OFF_LNB  (OFF_LNW + 32)               // [32]
#define SMEM_FLOATS (OFF_LNB + 32)

__global__ __launch_bounds__(256, 4) void main_kernel(
    const float* __restrict__ ori,
    const float* __restrict__ lno_w, const float* __restrict__ lno_b,
    const float* __restrict__ conv_w,
    float* __restrict__ out)
{
    extern __shared__ float sm[];
    float* wp   = sm + OFF_WP;
    float* part = sm + OFF_PART;
    float* mixs = sm + OFF_MIX;
    float* c0s  = sm + OFF_C0;
    float* cws  = sm + OFF_CWS;
    float* lnw  = sm + OFF_LNW;
    float* lnb  = sm + OFF_LNB;

    const int tid  = threadIdx.x;
    const int lane = tid & 31;
    const int w    = tid >> 5;
    const int b    = blockIdx.x >> 5;
    const int x    = blockIdx.x & 31;

    const float* obase = ori + ((size_t)(b * 1024 + x * FSZ)) * HID;

    if (tid < 32) { lnw[tid] = lno_w[tid]; lnb[tid] = lno_b[tid]; }
    if (tid < 8)  cws[tid] = g_cwsum[tid];

    // ---- Phase S: stats + w' (threads < 192, float4 column j = tid) ----
    float c0p[8];
    #pragma unroll
    for (int n = 0; n < 8; n++) c0p[n] = 0.f;

    if (tid < 192) {
        float4 s4 = make_float4(0.f, 0.f, 0.f, 0.f);
        float4 q4 = make_float4(0.f, 0.f, 0.f, 0.f);
        #pragma unroll
        for (int y = 0; y < FSZ; y++) {
            float4 o4 = *(const float4*)&obase[(size_t)y * HID + 4 * tid];
            s4.x += o4.x; s4.y += o4.y; s4.z += o4.z; s4.w += o4.w;
            q4.x += o4.x * o4.x; q4.y += o4.y * o4.y;
            q4.z += o4.z * o4.z; q4.w += o4.w * o4.w;
        }
        const float inv = 1.f / FSZ, eps = (float)FSZ;
        float4 mu4 = make_float4(s4.x * inv, s4.y * inv, s4.z * inv, s4.w * inv);
        float4 rs4;
        rs4.x = rsqrtf(q4.x * inv - mu4.x * mu4.x + eps);
        rs4.y = rsqrtf(q4.y * inv - mu4.y * mu4.y + eps);
        rs4.z = rsqrtf(q4.z * inv - mu4.z * mu4.z + eps);
        rs4.w = rsqrtf(q4.w * inv - mu4.w * mu4.w + eps);
        float4 mr4 = make_float4(mu4.x * rs4.x, mu4.y * rs4.y,
                                 mu4.z * rs4.z, mu4.w * rs4.w);
        #pragma unroll
        for (int n = 0; n < 8; n++) {
            float4 c4 = *(const float4*)&conv_w[n * HID + 4 * tid];
            float4 w4 = make_float4(c4.x * rs4.x, c4.y * rs4.y,
                                    c4.z * rs4.z, c4.w * rs4.w);
            *(float4*)&wp[n * HID + 4 * tid] = w4;
            c0p[n] += c4.x * mr4.x + c4.y * mr4.y + c4.z * mr4.z + c4.w * mr4.w;
        }
    }
    // c0 reduce: warps 0..5 butterfly, leader stages into part[0..47]
    if (w < 6) {
        #pragma unroll
        for (int n = 0; n < 8; n++) {
            #pragma unroll
            for (int o = 16; o; o >>= 1)
                c0p[n] += __shfl_xor_sync(0xffffffffu, c0p[n], o);
        }
        if (lane == 0) {
            #pragma unroll
            for (int n = 0; n < 8; n++) part[w * 8 + n] = c0p[n];
        }
    }
    __syncthreads();
    if (tid < 8) {
        float s = 0.f;
        #pragma unroll
        for (int ww = 0; ww < 6; ww++) s += part[ww * 8 + tid];
        c0s[tid] = s;
    }
    // Staging floats 0..47 are later overwritten only by warp 0's GEMM stores;
    // the tid<8 reads above precede those in warp-0 program order. c0s is read
    // only after the post-GEMM __syncthreads.

    // ---- Phase G: GEMM, rows y = w + 8*yy, re-read ori from L2 (streaming) ----
    float acc[4][8];
    #pragma unroll
    for (int yy = 0; yy < 4; yy++)
        #pragma unroll
        for (int n = 0; n < 8; n++) acc[yy][n] = 0.f;

    #pragma unroll
    for (int k = 0; k < 6; k++) {
        const int j = lane + 32 * k;
        float4 o4[4];
        #pragma unroll
        for (int yy = 0; yy < 4; yy++)
            o4[yy] = ld_cs_v4(&obase[(size_t)(w + 8 * yy) * HID + 4 * j]);
        #pragma unroll
        for (int n = 0; n < 8; n++) {
            float4 w4 = *(const float4*)&wp[n * HID + 4 * j];
            #pragma unroll
            for (int yy = 0; yy < 4; yy++) {
                acc[yy][n] = fmaf(w4.x, o4[yy].x, acc[yy][n]);
                acc[yy][n] = fmaf(w4.y, o4[yy].y, acc[yy][n]);
                acc[yy][n] = fmaf(w4.z, o4[yy].z, acc[yy][n]);
                acc[yy][n] = fmaf(w4.w, o4[yy].w, acc[yy][n]);
            }
        }
    }
    // 2-step butterfly pre-reduce over lane groups of 4, then 8 lanes store
    // part[r][sub]: r warp-uniform, sub = lane>>2 consecutive -> conflict-free
    {
        const int sub = lane >> 2;
        #pragma unroll
        for (int yy = 0; yy < 4; yy++) {
            #pragma unroll
            for (int n = 0; n < 8; n++) {
                float v = acc[yy][n];
                v += __shfl_xor_sync(0xffffffffu, v, 1);
                v += __shfl_xor_sync(0xffffffffu, v, 2);
                acc[yy][n] = v;
            }
        }
        if ((lane & 3) == 0) {
            #pragma unroll
            for (int yy = 0; yy < 4; yy++) {
                const int rbase = (w + 8 * yy) * 8;
                #pragma unroll
                for (int n = 0; n < 8; n++)
                    part[(rbase + n) * PSTRIDE + sub] = acc[yy][n];
            }
        }
    }
    __syncthreads();    // acc dead here

    // ---- Phase F: thread tid reduces row tid (r = y*8+n) + sigmoid ----
    {
        const int n = tid & 7, y = tid >> 3;
        float P = 0.f;
        #pragma unroll
        for (int s = 0; s < 8; s++)
            P += part[tid * PSTRIDE + s];   // 9*tid mod 32: permutation, no conflicts
        P -= c0s[n];
        float v = lnw[y] * P + lnb[y] * cws[n];
        mixs[n * 32 + y] = 1.f / (1.f + __expf(-v));
    }
    __syncthreads();

    // ---- Phase O: load t NOW (acc long dead -> no reg collision), then out ----
    if (tid < 192) {
        float4 tv[NTOK];
        #pragma unroll
        for (int n = 0; n < NTOK; n++)
            tv[n] = *(const float4*)&g_t[((size_t)b * NTOK + n) * HID + 4 * tid];

        float* ob = out + ((size_t)(b * 1024 + x * FSZ)) * HID;
        #pragma unroll
        for (int y = 0; y < FSZ; y++) {
            float4 r = make_float4(0.f, 0.f, 0.f, 0.f);
            #pragma unroll
            for (int n = 0; n < NTOK; n++) {
                float mn = mixs[n * 32 + y];  // warp-uniform -> broadcast LDS
                r.x += tv[n].x * mn; r.y += tv[n].y * mn;
                r.z += tv[n].z * mn; r.w += tv[n].w * mn;
            }
            st_cs_v4(&ob[(size_t)y * HID + 4 * tid], r);
        }
    }
}

// ---------------------------------------------------------------------------
extern "C" void kernel_launch(void* const* d_in, const int* in_sizes, int n_in,
                              void* d_out, int out_size)
{
    const float* token = (const float*)d_in[0];
    const float* ori   = (const float*)d_in[1];
    const float* ln1_w = (const float*)d_in[2];
    const float* ln1_b = (const float*)d_in[3];
    const float* lin_w = (const float*)d_in[4];
    const float* lin_b = (const float*)d_in[5];
    const float* ln2_w = (const float*)d_in[6];
    const float* ln2_b = (const float*)d_in[7];
    const float* lno_w = (const float*)d_in[8];
    const float* lno_b = (const float*)d_in[9];
    const float* conv_w= (const float*)d_in[10];

    const int smem_bytes = SMEM_FLOATS * sizeof(float);
    cudaFuncSetAttribute(main_kernel, cudaFuncAttributeMaxDynamicSharedMemorySize, smem_bytes);

    prep_kernel<<<BATCH + 1, 256>>>(token, ln1_w, ln1_b, lin_w, lin_b,
                                    ln2_w, ln2_b, conv_w);
    main_kernel<<<BATCH * FSZ, 256, smem_bytes>>>(ori, lno_w, lno_b, conv_w,
                                                  (float*)d_out);
}

// round 14
// speedup vs baseline: 1.1708x; 1.1708x over previous
#include <cuda_runtime.h>

#define HID 768
#define NTOK 8
#define FSZ 32
#define BATCH 64

__device__ __forceinline__ void st_cs_v4(float* p, float4 v) {
    asm volatile("st.global.cs.v4.f32 [%0], {%1,%2,%3,%4};"
                 :: "l"(p), "f"(v.x), "f"(v.y), "f"(v.z), "f"(v.w) : "memory");
}
__device__ __forceinline__ float4 ld_cs_v4(const float* p) {
    float4 v;
    asm volatile("ld.global.cs.v4.f32 {%0,%1,%2,%3}, [%4];"
                 : "=f"(v.x), "=f"(v.y), "=f"(v.z), "=f"(v.w) : "l"(p));
    return v;
}

// ---------------------------------------------------------------------------
// Single fused kernel: 256 threads, 3 blocks/SM, ~59 KB smem.
// Warp specialization during Phase S:
//   warps 0-5 (192 thr): ori stats (mu,rs per h) -> w' = conv_w*rs, c0 partial
//   warps 6-7 ( 64 thr): t = LN2(Lin(LN1(token[b]))) -> ts smem; cwsum
//                        (internal sync: named barrier 7, 64 threads)
// Then all 8 warps: GEMM (re-read ori from L2) -> shfl pre-reduce -> part
//                   reduce+sigmoid -> mix; out = t^T mix from ts.
// ---------------------------------------------------------------------------
#define PSTRIDE 9
#define OFF_WP   0                            // [8][768]   w' = conv_w * rs
#define OFF_TS   (OFF_WP + 8 * HID)           // [8][768]   t tile
#define OFF_PART (OFF_TS + NTOK * HID)        // [256][9]   (also c0 staging [48])
#define OFF_MIX  (OFF_PART + 256 * PSTRIDE)   // [8][32]
#define OFF_C0   (OFF_MIX + 256)              // [8]
#define OFF_CWS  (OFF_C0 + 8)                 // [8]
#define OFF_LNW  (OFF_CWS + 8)                // [32]
#define OFF_LNB  (OFF_LNW + 32)               // [32]
#define OFF_LW   (OFF_LNB + 32)               // [72] lin_w + lin_b
#define SMEM_FLOATS (OFF_LW + 72)

__global__ __launch_bounds__(256, 3) void fused_kernel(
    const float* __restrict__ token,
    const float* __restrict__ ori,
    const float* __restrict__ ln1_w, const float* __restrict__ ln1_b,
    const float* __restrict__ lin_w, const float* __restrict__ lin_b,
    const float* __restrict__ ln2_w, const float* __restrict__ ln2_b,
    const float* __restrict__ lno_w, const float* __restrict__ lno_b,
    const float* __restrict__ conv_w,
    float* __restrict__ out)
{
    extern __shared__ float sm[];
    float* wp   = sm + OFF_WP;
    float* ts   = sm + OFF_TS;
    float* part = sm + OFF_PART;
    float* mixs = sm + OFF_MIX;
    float* c0s  = sm + OFF_C0;
    float* cws  = sm + OFF_CWS;
    float* lnw  = sm + OFF_LNW;
    float* lnb  = sm + OFF_LNB;
    float* lw   = sm + OFF_LW;

    const int tid  = threadIdx.x;
    const int lane = tid & 31;
    const int w    = tid >> 5;
    const int b    = blockIdx.x >> 5;
    const int x    = blockIdx.x & 31;

    const float* obase = ori + ((size_t)(b * 1024 + x * FSZ)) * HID;

    if (tid < 32) { lnw[tid] = lno_w[tid]; lnb[tid] = lno_b[tid]; }

    if (tid < 192) {
        // ================= Warps 0-5: Phase S (stats + w' + c0) =============
        float c0p[8];
        #pragma unroll
        for (int n = 0; n < 8; n++) c0p[n] = 0.f;

        float4 s4 = make_float4(0.f, 0.f, 0.f, 0.f);
        float4 q4 = make_float4(0.f, 0.f, 0.f, 0.f);
        #pragma unroll
        for (int y = 0; y < FSZ; y++) {
            float4 o4 = *(const float4*)&obase[(size_t)y * HID + 4 * tid];
            s4.x += o4.x; s4.y += o4.y; s4.z += o4.z; s4.w += o4.w;
            q4.x += o4.x * o4.x; q4.y += o4.y * o4.y;
            q4.z += o4.z * o4.z; q4.w += o4.w * o4.w;
        }
        const float inv = 1.f / FSZ, eps = (float)FSZ;
        float4 mu4 = make_float4(s4.x * inv, s4.y * inv, s4.z * inv, s4.w * inv);
        float4 rs4;
        rs4.x = rsqrtf(q4.x * inv - mu4.x * mu4.x + eps);
        rs4.y = rsqrtf(q4.y * inv - mu4.y * mu4.y + eps);
        rs4.z = rsqrtf(q4.z * inv - mu4.z * mu4.z + eps);
        rs4.w = rsqrtf(q4.w * inv - mu4.w * mu4.w + eps);
        float4 mr4 = make_float4(mu4.x * rs4.x, mu4.y * rs4.y,
                                 mu4.z * rs4.z, mu4.w * rs4.w);
        #pragma unroll
        for (int n = 0; n < 8; n++) {
            float4 c4 = *(const float4*)&conv_w[n * HID + 4 * tid];
            float4 w4 = make_float4(c4.x * rs4.x, c4.y * rs4.y,
                                    c4.z * rs4.z, c4.w * rs4.w);
            *(float4*)&wp[n * HID + 4 * tid] = w4;
            c0p[n] += c4.x * mr4.x + c4.y * mr4.y + c4.z * mr4.z + c4.w * mr4.w;
        }
        // c0 butterfly within each of warps 0..5, leader stages to part[w*8+n]
        #pragma unroll
        for (int n = 0; n < 8; n++) {
            #pragma unroll
            for (int o = 16; o; o >>= 1)
                c0p[n] += __shfl_xor_sync(0xffffffffu, c0p[n], o);
        }
        if (lane == 0) {
            #pragma unroll
            for (int n = 0; n < 8; n++) part[w * 8 + n] = c0p[n];
        }
    } else {
        // ================= Warps 6-7: t pipeline + cwsum ====================
        const int wt  = w - 6;            // 0 or 1
        const int t2  = tid - 192;        // 0..63

        // stage lin weights (before first named barrier)
        if (t2 < 64) lw[t2] = lin_w[t2];
        if (t2 < 8)  lw[64 + t2] = lin_b[t2];

        // load token[b] -> ts (float4, coalesced across 64 threads)
        {
            const float4* tsrc = (const float4*)(token + (size_t)b * NTOK * HID);
            #pragma unroll
            for (int i = t2; i < NTOK * HID / 4; i += 64)
                *(float4*)&ts[4 * i] = __ldg(&tsrc[i]);
        }
        // cwsum: warp wt covers conv_w rows 4*wt..4*wt+3
        #pragma unroll
        for (int r = 0; r < 4; r++) {
            const int row = wt * 4 + r;
            float cs = 0.f;
            #pragma unroll
            for (int k = 0; k < 24; k++) cs += __ldg(&conv_w[row * HID + lane + 32 * k]);
            #pragma unroll
            for (int o = 16; o; o >>= 1) cs += __shfl_xor_sync(0xffffffffu, cs, o);
            if (lane == 0) cws[row] = cs;
        }
        asm volatile("bar.sync 7, 64;" ::: "memory");   // token load complete

        // LN1: warp wt -> rows 4*wt..4*wt+3
        #pragma unroll
        for (int r = 0; r < 4; r++) {
            const int row = wt * 4 + r;
            float sum = 0.f, sq = 0.f;
            #pragma unroll
            for (int k = 0; k < 24; k++) {
                float v = ts[row * HID + lane + 32 * k];
                sum += v; sq += v * v;
            }
            #pragma unroll
            for (int o = 16; o; o >>= 1) {
                sum += __shfl_xor_sync(0xffffffffu, sum, o);
                sq  += __shfl_xor_sync(0xffffffffu, sq,  o);
            }
            float mu = sum * (1.f / HID);
            float rs = rsqrtf(sq * (1.f / HID) - mu * mu + 1e-5f);
            #pragma unroll
            for (int k = 0; k < 24; k++) {
                const int h = lane + 32 * k;
                ts[row * HID + h] = (ts[row * HID + h] - mu) * rs
                                    * __ldg(&ln1_w[h]) + __ldg(&ln1_b[h]);
            }
        }
        asm volatile("bar.sync 7, 64;" ::: "memory");

        // Linear over token dim: thread t2 owns 12 h-columns
        #pragma unroll
        for (int k = 0; k < 12; k++) {
            const int h = t2 + 64 * k;
            float v[NTOK];
            #pragma unroll
            for (int n = 0; n < NTOK; n++) v[n] = ts[n * HID + h];
            #pragma unroll
            for (int m = 0; m < NTOK; m++) {
                float a = lw[64 + m];
                #pragma unroll
                for (int n = 0; n < NTOK; n++) a += lw[m * NTOK + n] * v[n];
                ts[m * HID + h] = a;
            }
        }
        asm volatile("bar.sync 7, 64;" ::: "memory");

        // LN2 -> final t in ts
        #pragma unroll
        for (int r = 0; r < 4; r++) {
            const int row = wt * 4 + r;
            float sum = 0.f, sq = 0.f;
            #pragma unroll
            for (int k = 0; k < 24; k++) {
                float v = ts[row * HID + lane + 32 * k];
                sum += v; sq += v * v;
            }
            #pragma unroll
            for (int o = 16; o; o >>= 1) {
                sum += __shfl_xor_sync(0xffffffffu, sum, o);
                sq  += __shfl_xor_sync(0xffffffffu, sq,  o);
            }
            float mu = sum * (1.f / HID);
            float rs = rsqrtf(sq * (1.f / HID) - mu * mu + 1e-5f);
            #pragma unroll
            for (int k = 0; k < 24; k++) {
                const int h = lane + 32 * k;
                ts[row * HID + h] = (ts[row * HID + h] - mu) * rs
                                    * __ldg(&ln2_w[h]) + __ldg(&ln2_b[h]);
            }
        }
    }
    __syncthreads();   // wp, ts, cws, c0 staging all visible

    if (tid < 8) {
        float s = 0.f;
        #pragma unroll
        for (int ww = 0; ww < 6; ww++) s += part[ww * 8 + tid];
        c0s[tid] = s;
    }
    // Staging floats 0..47 are later overwritten only by warp 0's GEMM stores;
    // the tid<8 reads above precede those in warp-0 program order. c0s is read
    // only after the post-GEMM __syncthreads.

    // ---- Phase G: GEMM, rows y = w + 8*yy, re-read ori from L2 (streaming) ----
    float acc[4][8];
    #pragma unroll
    for (int yy = 0; yy < 4; yy++)
        #pragma unroll
        for (int n = 0; n < 8; n++) acc[yy][n] = 0.f;

    #pragma unroll
    for (int k = 0; k < 6; k++) {
        const int j = lane + 32 * k;
        float4 o4[4];
        #pragma unroll
        for (int yy = 0; yy < 4; yy++)
            o4[yy] = ld_cs_v4(&obase[(size_t)(w + 8 * yy) * HID + 4 * j]);
        #pragma unroll
        for (int n = 0; n < 8; n++) {
            float4 w4 = *(const float4*)&wp[n * HID + 4 * j];
            #pragma unroll
            for (int yy = 0; yy < 4; yy++) {
                acc[yy][n] = fmaf(w4.x, o4[yy].x, acc[yy][n]);
                acc[yy][n] = fmaf(w4.y, o4[yy].y, acc[yy][n]);
                acc[yy][n] = fmaf(w4.z, o4[yy].z, acc[yy][n]);
                acc[yy][n] = fmaf(w4.w, o4[yy].w, acc[yy][n]);
            }
        }
    }
    // 2-step butterfly pre-reduce (lane groups of 4), 8 lanes store part[r][sub]
    {
        const int sub = lane >> 2;
        #pragma unroll
        for (int yy = 0; yy < 4; yy++) {
            #pragma unroll
            for (int n = 0; n < 8; n++) {
                float v = acc[yy][n];
                v += __shfl_xor_sync(0xffffffffu, v, 1);
                v += __shfl_xor_sync(0xffffffffu, v, 2);
                acc[yy][n] = v;
            }
        }
        if ((lane & 3) == 0) {
            #pragma unroll
            for (int yy = 0; yy < 4; yy++) {
                const int rbase = (w + 8 * yy) * 8;
                #pragma unroll
                for (int n = 0; n < 8; n++)
                    part[(rbase + n) * PSTRIDE + sub] = acc[yy][n];
            }
        }
    }
    __syncthreads();

    // ---- Phase F: thread tid reduces row tid (r = y*8+n) + sigmoid ----
    {
        const int n = tid & 7, y = tid >> 3;
        float P = 0.f;
        #pragma unroll
        for (int s = 0; s < 8; s++)
            P += part[tid * PSTRIDE + s];   // 9*tid mod 32: permutation, no conflicts
        P -= c0s[n];
        float v = lnw[y] * P + lnb[y] * cws[n];
        mixs[n * 32 + y] = 1.f / (1.f + __expf(-v));
    }
    __syncthreads();

    // ---- Phase O: tv from ts (one-time LDS), out = sum_n tv*mix ----
    if (tid < 192) {
        float4 tv[NTOK];
        #pragma unroll
        for (int n = 0; n < NTOK; n++)
            tv[n] = *(const float4*)&ts[n * HID + 4 * tid];

        float* ob = out + ((size_t)(b * 1024 + x * FSZ)) * HID;
        #pragma unroll
        for (int y = 0; y < FSZ; y++) {
            float4 r = make_float4(0.f, 0.f, 0.f, 0.f);
            #pragma unroll
            for (int n = 0; n < NTOK; n++) {
                float mn = mixs[n * 32 + y];  // warp-uniform -> broadcast LDS
                r.x += tv[n].x * mn; r.y += tv[n].y * mn;
                r.z += tv[n].z * mn; r.w += tv[n].w * mn;
            }
            st_cs_v4(&ob[(size_t)y * HID + 4 * tid], r);
        }
    }
}

// ---------------------------------------------------------------------------
extern "C" void kernel_launch(void* const* d_in, const int* in_sizes, int n_in,
                              void* d_out, int out_size)
{
    const float* token = (const float*)d_in[0];
    const float* ori   = (const float*)d_in[1];
    const float* ln1_w = (const float*)d_in[2];
    const float* ln1_b = (const float*)d_in[3];
    const float* lin_w = (const float*)d_in[4];
    const float* lin_b = (const float*)d_in[5];
    const float* ln2_w = (const float*)d_in[6];
    const float* ln2_b = (const float*)d_in[7];
    const float* lno_w = (const float*)d_in[8];
    const float* lno_b = (const float*)d_in[9];
    const float* conv_w= (const float*)d_in[10];

    const int smem_bytes = SMEM_FLOATS * sizeof(float);
    cudaFuncSetAttribute(fused_kernel, cudaFuncAttributeMaxDynamicSharedMemorySize, smem_bytes);

    fused_kernel<<<BATCH * FSZ, 256, smem_bytes>>>(
        token, ori, ln1_w, ln1_b, lin_w, lin_b, ln2_w, ln2_b,
        lno_w, lno_b, conv_w, (float*)d_out);
}

// round 15
// speedup vs baseline: 1.4372x; 1.2275x over previous
#include <cuda_runtime.h>

#define HID 768
#define NTOK 8
#define FSZ 32
#define BATCH 64

__device__ float g_t[BATCH * NTOK * HID];
__device__ float g_cwsum[NTOK];

__device__ __forceinline__ void st_cs_v4(float* p, float4 v) {
    asm volatile("st.global.cs.v4.f32 [%0], {%1,%2,%3,%4};"
                 :: "l"(p), "f"(v.x), "f"(v.y), "f"(v.z), "f"(v.w) : "memory");
}
__device__ __forceinline__ float4 ld_cs_v4(const float* p) {
    float4 v;
    asm volatile("ld.global.cs.v4.f32 {%0,%1,%2,%3}, [%4];"
                 : "=f"(v.x), "=f"(v.y), "=f"(v.z), "=f"(v.w) : "l"(p));
    return v;
}

// ---------------------------------------------------------------------------
// Kernel 1 (rewritten): one block per batch, 768 threads, register-resident.
// Thread h owns column h of all 8 token rows. LN reductions: warp shfl ->
// [24][8] smem partials -> 8 threads finalize -> broadcast. Linear in regs.
// Block 64 computes cwsum.
// ---------------------------------------------------------------------------
__global__ __launch_bounds__(768) void prep_kernel(
    const float* __restrict__ token,
    const float* __restrict__ ln1_w, const float* __restrict__ ln1_b,
    const float* __restrict__ lin_w, const float* __restrict__ lin_b,
    const float* __restrict__ ln2_w, const float* __restrict__ ln2_b,
    const float* __restrict__ conv_w)
{
    __shared__ float rsum[24][8];
    __shared__ float rsq[24][8];
    __shared__ float stats[16];      // mu[0..7], rs[8..15]
    __shared__ float lw[72];         // lin_w (64) + lin_b (8)

    const int b    = blockIdx.x;
    const int tid  = threadIdx.x;
    const int lane = tid & 31;
    const int w    = tid >> 5;       // 24 warps

    if (b == BATCH) {                // cwsum block: warps 0-7, row w
        if (w < 8) {
            float cs = 0.f;
            #pragma unroll
            for (int k = 0; k < 24; k++) cs += __ldg(&conv_w[w * HID + lane + 32 * k]);
            #pragma unroll
            for (int o = 16; o; o >>= 1) cs += __shfl_xor_sync(0xffffffffu, cs, o);
            if (lane == 0) g_cwsum[w] = cs;
        }
        return;
    }

    if (tid < 64)                 lw[tid] = lin_w[tid];
    else if (tid < 72)            lw[tid] = lin_b[tid - 64];

    // load all 8 rows of column tid (coalesced per row)
    float xv[NTOK];
    #pragma unroll
    for (int n = 0; n < NTOK; n++)
        xv[n] = __ldg(&token[((size_t)b * NTOK + n) * HID + tid]);

    // ---- LN1 reductions ----
    #pragma unroll
    for (int n = 0; n < NTOK; n++) {
        float s = xv[n], q = xv[n] * xv[n];
        #pragma unroll
        for (int o = 16; o; o >>= 1) {
            s += __shfl_xor_sync(0xffffffffu, s, o);
            q += __shfl_xor_sync(0xffffffffu, q, o);
        }
        if (lane == 0) { rsum[w][n] = s; rsq[w][n] = q; }
    }
    __syncthreads();
    if (tid < 8) {
        float s = 0.f, q = 0.f;
        #pragma unroll
        for (int ww = 0; ww < 24; ww++) { s += rsum[ww][tid]; q += rsq[ww][tid]; }
        float mu = s * (1.f / HID);
        stats[tid]     = mu;
        stats[8 + tid] = rsqrtf(q * (1.f / HID) - mu * mu + 1e-5f);
    }
    __syncthreads();

    // apply LN1 affine
    {
        const float w1 = __ldg(&ln1_w[tid]), b1 = __ldg(&ln1_b[tid]);
        #pragma unroll
        for (int n = 0; n < NTOK; n++)
            xv[n] = (xv[n] - stats[n]) * stats[8 + n] * w1 + b1;
    }

    // ---- Linear over token dim (in registers) ----
    float ov[NTOK];
    #pragma unroll
    for (int m = 0; m < NTOK; m++) {
        float a = lw[64 + m];
        #pragma unroll
        for (int n = 0; n < NTOK; n++) a += lw[m * NTOK + n] * xv[n];
        ov[m] = a;
    }

    // ---- LN2 reductions ----
    #pragma unroll
    for (int n = 0; n < NTOK; n++) {
        float s = ov[n], q = ov[n] * ov[n];
        #pragma unroll
        for (int o = 16; o; o >>= 1) {
            s += __shfl_xor_sync(0xffffffffu, s, o);
            q += __shfl_xor_sync(0xffffffffu, q, o);
        }
        if (lane == 0) { rsum[w][n] = s; rsq[w][n] = q; }
    }
    __syncthreads();
    if (tid < 8) {
        float s = 0.f, q = 0.f;
        #pragma unroll
        for (int ww = 0; ww < 24; ww++) { s += rsum[ww][tid]; q += rsq[ww][tid]; }
        float mu = s * (1.f / HID);
        stats[tid]     = mu;
        stats[8 + tid] = rsqrtf(q * (1.f / HID) - mu * mu + 1e-5f);
    }
    __syncthreads();

    // apply LN2 affine + store (coalesced per row)
    {
        const float w2 = __ldg(&ln2_w[tid]), b2 = __ldg(&ln2_b[tid]);
        #pragma unroll
        for (int n = 0; n < NTOK; n++)
            g_t[((size_t)b * NTOK + n) * HID + tid] =
                (ov[n] - stats[n]) * stats[8 + n] * w2 + b2;
    }
}

// ---------------------------------------------------------------------------
// Kernel 2 (R12 body, 3 blocks/SM): 256 threads, ~35 KB smem, ~80 regs.
// ---------------------------------------------------------------------------
#define PSTRIDE 9
#define OFF_WP   0                            // [8][768]
#define OFF_PART (OFF_WP + 8 * HID)           // [256][9]  (also c0 staging [48])
#define OFF_MIX  (OFF_PART + 256 * PSTRIDE)   // [8][32]
#define OFF_C0   (OFF_MIX + 256)              // [8]
#define OFF_CWS  (OFF_C0 + 8)                 // [8]
#define OFF_LNW  (OFF_CWS + 8)                // [32]
#define OFF_LNB  (OFF_LNW + 32)               // [32]
#define SMEM_FLOATS (OFF_LNB + 32)

__global__ __launch_bounds__(256, 3) void main_kernel(
    const float* __restrict__ ori,
    const float* __restrict__ lno_w, const float* __restrict__ lno_b,
    const float* __restrict__ conv_w,
    float* __restrict__ out)
{
    extern __shared__ float sm[];
    float* wp   = sm + OFF_WP;
    float* part = sm + OFF_PART;
    float* mixs = sm + OFF_MIX;
    float* c0s  = sm + OFF_C0;
    float* cws  = sm + OFF_CWS;
    float* lnw  = sm + OFF_LNW;
    float* lnb  = sm + OFF_LNB;

    const int tid  = threadIdx.x;
    const int lane = tid & 31;
    const int w    = tid >> 5;
    const int b    = blockIdx.x >> 5;
    const int x    = blockIdx.x & 31;

    const float* obase = ori + ((size_t)(b * 1024 + x * FSZ)) * HID;

    if (tid < 32) { lnw[tid] = lno_w[tid]; lnb[tid] = lno_b[tid]; }
    if (tid < 8)  cws[tid] = g_cwsum[tid];

    // ---- Phase S: stats + w' (threads < 192, float4 column j = tid) ----
    float c0p[8];
    #pragma unroll
    for (int n = 0; n < 8; n++) c0p[n] = 0.f;

    if (tid < 192) {
        float4 s4 = make_float4(0.f, 0.f, 0.f, 0.f);
        float4 q4 = make_float4(0.f, 0.f, 0.f, 0.f);
        #pragma unroll
        for (int y = 0; y < FSZ; y++) {
            float4 o4 = *(const float4*)&obase[(size_t)y * HID + 4 * tid];
            s4.x += o4.x; s4.y += o4.y; s4.z += o4.z; s4.w += o4.w;
            q4.x += o4.x * o4.x; q4.y += o4.y * o4.y;
            q4.z += o4.z * o4.z; q4.w += o4.w * o4.w;
        }
        const float inv = 1.f / FSZ, eps = (float)FSZ;
        float4 mu4 = make_float4(s4.x * inv, s4.y * inv, s4.z * inv, s4.w * inv);
        float4 rs4;
        rs4.x = rsqrtf(q4.x * inv - mu4.x * mu4.x + eps);
        rs4.y = rsqrtf(q4.y * inv - mu4.y * mu4.y + eps);
        rs4.z = rsqrtf(q4.z * inv - mu4.z * mu4.z + eps);
        rs4.w = rsqrtf(q4.w * inv - mu4.w * mu4.w + eps);
        float4 mr4 = make_float4(mu4.x * rs4.x, mu4.y * rs4.y,
                                 mu4.z * rs4.z, mu4.w * rs4.w);
        #pragma unroll
        for (int n = 0; n < 8; n++) {
            float4 c4 = *(const float4*)&conv_w[n * HID + 4 * tid];
            float4 w4 = make_float4(c4.x * rs4.x, c4.y * rs4.y,
                                    c4.z * rs4.z, c4.w * rs4.w);
            *(float4*)&wp[n * HID + 4 * tid] = w4;
            c0p[n] += c4.x * mr4.x + c4.y * mr4.y + c4.z * mr4.z + c4.w * mr4.w;
        }
    }
    // c0 reduce: warps 0..5 butterfly, leader stages into part[0..47]
    if (w < 6) {
        #pragma unroll
        for (int n = 0; n < 8; n++) {
            #pragma unroll
            for (int o = 16; o; o >>= 1)
                c0p[n] += __shfl_xor_sync(0xffffffffu, c0p[n], o);
        }
        if (lane == 0) {
            #pragma unroll
            for (int n = 0; n < 8; n++) part[w * 8 + n] = c0p[n];
        }
    }
    __syncthreads();
    if (tid < 8) {
        float s = 0.f;
        #pragma unroll
        for (int ww = 0; ww < 6; ww++) s += part[ww * 8 + tid];
        c0s[tid] = s;
    }
    // Staging floats 0..47 are later overwritten only by warp 0's GEMM stores
    // (rows r<8 -> floats <72); the tid<8 reads above precede those in warp-0
    // program order. c0s is read only after the post-GEMM __syncthreads.

    // ---- Phase G: GEMM, rows y = w + 8*yy, re-read ori from L2 (streaming) ----
    float acc[4][8];
    #pragma unroll
    for (int yy = 0; yy < 4; yy++)
        #pragma unroll
        for (int n = 0; n < 8; n++) acc[yy][n] = 0.f;

    #pragma unroll
    for (int k = 0; k < 6; k++) {
        const int j = lane + 32 * k;
        float4 o4[4];
        #pragma unroll
        for (int yy = 0; yy < 4; yy++)
            o4[yy] = ld_cs_v4(&obase[(size_t)(w + 8 * yy) * HID + 4 * j]);
        #pragma unroll
        for (int n = 0; n < 8; n++) {
            float4 w4 = *(const float4*)&wp[n * HID + 4 * j];
            #pragma unroll
            for (int yy = 0; yy < 4; yy++) {
                acc[yy][n] = fmaf(w4.x, o4[yy].x, acc[yy][n]);
                acc[yy][n] = fmaf(w4.y, o4[yy].y, acc[yy][n]);
                acc[yy][n] = fmaf(w4.z, o4[yy].z, acc[yy][n]);
                acc[yy][n] = fmaf(w4.w, o4[yy].w, acc[yy][n]);
            }
        }
    }
    // 2-step butterfly pre-reduce (lane groups of 4); 8 lanes store part[r][sub]
    {
        const int sub = lane >> 2;
        #pragma unroll
        for (int yy = 0; yy < 4; yy++) {
            #pragma unroll
            for (int n = 0; n < 8; n++) {
                float v = acc[yy][n];
                v += __shfl_xor_sync(0xffffffffu, v, 1);
                v += __shfl_xor_sync(0xffffffffu, v, 2);
                acc[yy][n] = v;
            }
        }
        if ((lane & 3) == 0) {
            #pragma unroll
            for (int yy = 0; yy < 4; yy++) {
                const int rbase = (w + 8 * yy) * 8;
                #pragma unroll
                for (int n = 0; n < 8; n++)
                    part[(rbase + n) * PSTRIDE + sub] = acc[yy][n];
            }
        }
    }

    // prefetch t into registers (80-reg budget: no spill at 3 blocks/SM)
    float4 tv[NTOK];
    if (tid < 192) {
        #pragma unroll
        for (int n = 0; n < NTOK; n++)
            tv[n] = *(const float4*)&g_t[((size_t)b * NTOK + n) * HID + 4 * tid];
    }
    __syncthreads();

    // ---- Phase F: thread tid reduces row tid (r = y*8+n) + sigmoid ----
    {
        const int n = tid & 7, y = tid >> 3;
        float P = 0.f;
        #pragma unroll
        for (int s = 0; s < 8; s++)
            P += part[tid * PSTRIDE + s];   // 9*tid mod 32: permutation, no conflicts
        P -= c0s[n];
        float v = lnw[y] * P + lnb[y] * cws[n];
        mixs[n * 32 + y] = 1.f / (1.f + __expf(-v));
    }
    __syncthreads();

    // ---- Phase O: out[y][4*tid..+4) = sum_n tv[n]*mix[n][y] ----
    if (tid < 192) {
        float* ob = out + ((size_t)(b * 1024 + x * FSZ)) * HID;
        #pragma unroll
        for (int y = 0; y < FSZ; y++) {
            float4 r = make_float4(0.f, 0.f, 0.f, 0.f);
            #pragma unroll
            for (int n = 0; n < NTOK; n++) {
                float mn = mixs[n * 32 + y];  // warp-uniform -> broadcast LDS
                r.x += tv[n].x * mn; r.y += tv[n].y * mn;
                r.z += tv[n].z * mn; r.w += tv[n].w * mn;
            }
            st_cs_v4(&ob[(size_t)y * HID + 4 * tid], r);
        }
    }
}

// ---------------------------------------------------------------------------
extern "C" void kernel_launch(void* const* d_in, const int* in_sizes, int n_in,
                              void* d_out, int out_size)
{
    const float* token = (const float*)d_in[0];
    const float* ori   = (const float*)d_in[1];
    const float* ln1_w = (const float*)d_in[2];
    const float* ln1_b = (const float*)d_in[3];
    const float* lin_w = (const float*)d_in[4];
    const float* lin_b = (const float*)d_in[5];
    const float* ln2_w = (const float*)d_in[6];
    const float* ln2_b = (const float*)d_in[7];
    const float* lno_w = (const float*)d_in[8];
    const float* lno_b = (const float*)d_in[9];
    const float* conv_w= (const float*)d_in[10];

    const int smem_bytes = SMEM_FLOATS * sizeof(float);
    cudaFuncSetAttribute(main_kernel, cudaFuncAttributeMaxDynamicSharedMemorySize, smem_bytes);

    prep_kernel<<<BATCH + 1, 768>>>(token, ln1_w, ln1_b, lin_w, lin_b,
                                    ln2_w, ln2_b, conv_w);
    main_kernel<<<BATCH * FSZ, 256, smem_bytes>>>(ori, lno_w, lno_b, conv_w,
                                                  (float*)d_out);
}

// round 17
// speedup vs baseline: 1.7118x; 1.1911x over previous
#include <cuda_runtime.h>

#define HID 768
#define NTOK 8
#define FSZ 32
#define BATCH 64

__device__ float g_t[BATCH * NTOK * HID];
__device__ float g_cwsum[NTOK];

__device__ __forceinline__ void st_cs_v4(float* p, float4 v) {
    asm volatile("st.global.cs.v4.f32 [%0], {%1,%2,%3,%4};"
                 :: "l"(p), "f"(v.x), "f"(v.y), "f"(v.z), "f"(v.w) : "memory");
}
__device__ __forceinline__ float4 ld_cs_v4(const float* p) {
    float4 v;
    asm volatile("ld.global.cs.v4.f32 {%0,%1,%2,%3}, [%4];"
                 : "=f"(v.x), "=f"(v.y), "=f"(v.z), "=f"(v.w) : "l"(p));
    return v;
}

// ---------------------------------------------------------------------------
// Kernel 1: one block per batch, 768 threads, register-resident t pipeline.
// Triggers PDL dependents at entry so main can start concurrently.
// ---------------------------------------------------------------------------
__global__ __launch_bounds__(768) void prep_kernel(
    const float* __restrict__ token,
    const float* __restrict__ ln1_w, const float* __restrict__ ln1_b,
    const float* __restrict__ lin_w, const float* __restrict__ lin_b,
    const float* __restrict__ ln2_w, const float* __restrict__ ln2_b,
    const float* __restrict__ conv_w)
{
    asm volatile("griddepcontrol.launch_dependents;");

    __shared__ float rsum[24][8];
    __shared__ float rsq[24][8];
    __shared__ float stats[16];      // mu[0..7], rs[8..15]
    __shared__ float lw[72];         // lin_w (64) + lin_b (8)

    const int b    = blockIdx.x;
    const int tid  = threadIdx.x;
    const int lane = tid & 31;
    const int w    = tid >> 5;       // 24 warps

    if (b == BATCH) {                // cwsum block: warps 0-7, row w
        if (w < 8) {
            float cs = 0.f;
            #pragma unroll
            for (int k = 0; k < 24; k++) cs += __ldg(&conv_w[w * HID + lane + 32 * k]);
            #pragma unroll
            for (int o = 16; o; o >>= 1) cs += __shfl_xor_sync(0xffffffffu, cs, o);
            if (lane == 0) g_cwsum[w] = cs;
        }
        return;
    }

    if (tid < 64)      lw[tid] = lin_w[tid];
    else if (tid < 72) lw[tid] = lin_b[tid - 64];

    // thread tid owns column tid of all 8 token rows
    float xv[NTOK];
    #pragma unroll
    for (int n = 0; n < NTOK; n++)
        xv[n] = __ldg(&token[((size_t)b * NTOK + n) * HID + tid]);

    // ---- LN1 reductions ----
    #pragma unroll
    for (int n = 0; n < NTOK; n++) {
        float s = xv[n], q = xv[n] * xv[n];
        #pragma unroll
        for (int o = 16; o; o >>= 1) {
            s += __shfl_xor_sync(0xffffffffu, s, o);
            q += __shfl_xor_sync(0xffffffffu, q, o);
        }
        if (lane == 0) { rsum[w][n] = s; rsq[w][n] = q; }
    }
    __syncthreads();
    if (tid < 8) {
        float s = 0.f, q = 0.f;
        #pragma unroll
        for (int ww = 0; ww < 24; ww++) { s += rsum[ww][tid]; q += rsq[ww][tid]; }
        float mu = s * (1.f / HID);
        stats[tid]     = mu;
        stats[8 + tid] = rsqrtf(q * (1.f / HID) - mu * mu + 1e-5f);
    }
    __syncthreads();

    {   // LN1 affine
        const float w1 = __ldg(&ln1_w[tid]), b1 = __ldg(&ln1_b[tid]);
        #pragma unroll
        for (int n = 0; n < NTOK; n++)
            xv[n] = (xv[n] - stats[n]) * stats[8 + n] * w1 + b1;
    }

    // ---- Linear over token dim (registers) ----
    float ov[NTOK];
    #pragma unroll
    for (int m = 0; m < NTOK; m++) {
        float a = lw[64 + m];
        #pragma unroll
        for (int n = 0; n < NTOK; n++) a += lw[m * NTOK + n] * xv[n];
        ov[m] = a;
    }

    // ---- LN2 reductions ----
    #pragma unroll
    for (int n = 0; n < NTOK; n++) {
        float s = ov[n], q = ov[n] * ov[n];
        #pragma unroll
        for (int o = 16; o; o >>= 1) {
            s += __shfl_xor_sync(0xffffffffu, s, o);
            q += __shfl_xor_sync(0xffffffffu, q, o);
        }
        if (lane == 0) { rsum[w][n] = s; rsq[w][n] = q; }
    }
    __syncthreads();
    if (tid < 8) {
        float s = 0.f, q = 0.f;
        #pragma unroll
        for (int ww = 0; ww < 24; ww++) { s += rsum[ww][tid]; q += rsq[ww][tid]; }
        float mu = s * (1.f / HID);
        stats[tid]     = mu;
        stats[8 + tid] = rsqrtf(q * (1.f / HID) - mu * mu + 1e-5f);
    }
    __syncthreads();

    {   // LN2 affine + store
        const float w2 = __ldg(&ln2_w[tid]), b2 = __ldg(&ln2_b[tid]);
        #pragma unroll
        for (int n = 0; n < NTOK; n++)
            g_t[((size_t)b * NTOK + n) * HID + tid] =
                (ov[n] - stats[n]) * stats[8 + n] * w2 + b2;
    }
}

// ---------------------------------------------------------------------------
// Kernel 2 (R11 body): 256 threads, 3 blocks/SM, ~60 KB smem, ~80 regs.
// PDL: griddepcontrol.wait before first use of prep outputs (g_t, g_cwsum).
// ---------------------------------------------------------------------------
#define PSTRIDE 33
#define OFF_WP   0                            // [8][768]
#define OFF_PART (OFF_WP + 8 * HID)           // [256][33]  (also c0 staging [48])
#define OFF_MIX  (OFF_PART + 256 * PSTRIDE)   // [8][32]
#define OFF_C0   (OFF_MIX + 256)              // [8]
#define OFF_CWS  (OFF_C0 + 8)                 // [8]
#define OFF_LNW  (OFF_CWS + 8)                // [32]
#define OFF_LNB  (OFF_LNW + 32)               // [32]
#define SMEM_FLOATS (OFF_LNB + 32)

__global__ __launch_bounds__(256, 3) void main_kernel(
    const float* __restrict__ ori,
    const float* __restrict__ lno_w, const float* __restrict__ lno_b,
    const float* __restrict__ conv_w,
    float* __restrict__ out)
{
    extern __shared__ float sm[];
    float* wp   = sm + OFF_WP;
    float* part = sm + OFF_PART;
    float* mixs = sm + OFF_MIX;
    float* c0s  = sm + OFF_C0;
    float* cws  = sm + OFF_CWS;
    float* lnw  = sm + OFF_LNW;
    float* lnb  = sm + OFF_LNB;

    const int tid  = threadIdx.x;
    const int lane = tid & 31;
    const int w    = tid >> 5;
    const int b    = blockIdx.x >> 5;
    const int x    = blockIdx.x & 31;

    const float* obase = ori + ((size_t)(b * 1024 + x * FSZ)) * HID;

    if (tid < 32) { lnw[tid] = lno_w[tid]; lnb[tid] = lno_b[tid]; }
    // NOTE: g_cwsum is a prep output — loaded only after griddepcontrol.wait.

    // ---- Phase S: stats + w' (threads < 192, float4 column j = tid) ----
    float c0p[8];
    #pragma unroll
    for (int n = 0; n < 8; n++) c0p[n] = 0.f;

    if (tid < 192) {
        float4 s4 = make_float4(0.f, 0.f, 0.f, 0.f);
        float4 q4 = make_float4(0.f, 0.f, 0.f, 0.f);
        #pragma unroll
        for (int y = 0; y < FSZ; y++) {
            float4 o4 = *(const float4*)&obase[(size_t)y * HID + 4 * tid];
            s4.x += o4.x; s4.y += o4.y; s4.z += o4.z; s4.w += o4.w;
            q4.x += o4.x * o4.x; q4.y += o4.y * o4.y;
            q4.z += o4.z * o4.z; q4.w += o4.w * o4.w;
        }
        const float inv = 1.f / FSZ, eps = (float)FSZ;
        float4 mu4 = make_float4(s4.x * inv, s4.y * inv, s4.z * inv, s4.w * inv);
        float4 rs4;
        rs4.x = rsqrtf(q4.x * inv - mu4.x * mu4.x + eps);
        rs4.y = rsqrtf(q4.y * inv - mu4.y * mu4.y + eps);
        rs4.z = rsqrtf(q4.z * inv - mu4.z * mu4.z + eps);
        rs4.w = rsqrtf(q4.w * inv - mu4.w * mu4.w + eps);
        float4 mr4 = make_float4(mu4.x * rs4.x, mu4.y * rs4.y,
                                 mu4.z * rs4.z, mu4.w * rs4.w);
        #pragma unroll
        for (int n = 0; n < 8; n++) {
            float4 c4 = *(const float4*)&conv_w[n * HID + 4 * tid];
            float4 w4 = make_float4(c4.x * rs4.x, c4.y * rs4.y,
                                    c4.z * rs4.z, c4.w * rs4.w);
            *(float4*)&wp[n * HID + 4 * tid] = w4;
            c0p[n] += c4.x * mr4.x + c4.y * mr4.y + c4.z * mr4.z + c4.w * mr4.w;
        }
    }
    // c0 reduce: warps 0..5 butterfly, leader stages into part[0..47]
    if (w < 6) {
        #pragma unroll
        for (int n = 0; n < 8; n++) {
            #pragma unroll
            for (int o = 16; o; o >>= 1)
                c0p[n] += __shfl_xor_sync(0xffffffffu, c0p[n], o);
        }
        if (lane == 0) {
            #pragma unroll
            for (int n = 0; n < 8; n++) part[w * 8 + n] = c0p[n];
        }
    }
    __syncthreads();
    if (tid < 8) {
        float s = 0.f;
        #pragma unroll
        for (int ww = 0; ww < 6; ww++) s += part[ww * 8 + tid];
        c0s[tid] = s;
    }
    // Staging floats 0..47 are later overwritten only by warp 0's own GEMM
    // stores; the tid<8 reads above precede those in warp-0 program order.
    // c0s is read only after the post-GEMM __syncthreads.

    // ---- Phase G: GEMM, rows y = w + 8*yy, re-read ori from L2 (streaming) ----
    float acc[4][8];
    #pragma unroll
    for (int yy = 0; yy < 4; yy++)
        #pragma unroll
        for (int n = 0; n < 8; n++) acc[yy][n] = 0.f;

    #pragma unroll
    for (int k = 0; k < 6; k++) {
        const int j = lane + 32 * k;
        float4 o4[4];
        #pragma unroll
        for (int yy = 0; yy < 4; yy++)
            o4[yy] = ld_cs_v4(&obase[(size_t)(w + 8 * yy) * HID + 4 * j]);
        #pragma unroll
        for (int n = 0; n < 8; n++) {
            float4 w4 = *(const float4*)&wp[n * HID + 4 * j];
            #pragma unroll
            for (int yy = 0; yy < 4; yy++) {
                acc[yy][n] = fmaf(w4.x, o4[yy].x, acc[yy][n]);
                acc[yy][n] = fmaf(w4.y, o4[yy].y, acc[yy][n]);
                acc[yy][n] = fmaf(w4.z, o4[yy].z, acc[yy][n]);
                acc[yy][n] = fmaf(w4.w, o4[yy].w, acc[yy][n]);
            }
        }
    }
    // scalar partial stores: r = (w+8*yy)*8+n warp-uniform, lane varies
    #pragma unroll
    for (int yy = 0; yy < 4; yy++) {
        const int rbase = (w + 8 * yy) * 8;
        #pragma unroll
        for (int n = 0; n < 8; n++)
            part[(rbase + n) * PSTRIDE + lane] = acc[yy][n];
    }

    // ---- PDL: prep outputs needed from here on ----
    asm volatile("griddepcontrol.wait;");
    if (tid < 8) cws[tid] = g_cwsum[tid];

    // prefetch t into registers (overlaps with sync + reduce)
    float4 tv[NTOK];
    if (tid < 192) {
        #pragma unroll
        for (int n = 0; n < NTOK; n++)
            tv[n] = *(const float4*)&g_t[((size_t)b * NTOK + n) * HID + 4 * tid];
    }
    __syncthreads();

    // ---- Phase F: thread tid reduces row tid (r = y*8+n) + sigmoid ----
    {
        const int n = tid & 7, y = tid >> 3;
        float P = 0.f;
        #pragma unroll
        for (int l = 0; l < 32; l++)
            P += part[tid * PSTRIDE + l];   // banks (tid+l)%32: conflict-free
        P -= c0s[n];
        float v = lnw[y] * P + lnb[y] * cws[n];
        mixs[n * 32 + y] = 1.f / (1.f + __expf(-v));
    }
    __syncthreads();

    // ---- Phase O: out[y][4*tid..+4) = sum_n tv[n]*mix[n][y] ----
    if (tid < 192) {
        float* ob = out + ((size_t)(b * 1024 + x * FSZ)) * HID;
        #pragma unroll
        for (int y = 0; y < FSZ; y++) {
            float4 r = make_float4(0.f, 0.f, 0.f, 0.f);
            #pragma unroll
            for (int n = 0; n < NTOK; n++) {
                float mn = mixs[n * 32 + y];  // warp-uniform -> broadcast LDS
                r.x += tv[n].x * mn; r.y += tv[n].y * mn;
                r.z += tv[n].z * mn; r.w += tv[n].w * mn;
            }
            st_cs_v4(&ob[(size_t)y * HID + 4 * tid], r);
        }
    }
}

// ---------------------------------------------------------------------------
extern "C" void kernel_launch(void* const* d_in, const int* in_sizes, int n_in,
                              void* d_out, int out_size)
{
    const float* token = (const float*)d_in[0];
    const float* ori   = (const float*)d_in[1];
    const float* ln1_w = (const float*)d_in[2];
    const float* ln1_b = (const float*)d_in[3];
    const float* lin_w = (const float*)d_in[4];
    const float* lin_b = (const float*)d_in[5];
    const float* ln2_w = (const float*)d_in[6];
    const float* ln2_b = (const float*)d_in[7];
    const float* lno_w = (const float*)d_in[8];
    const float* lno_b = (const float*)d_in[9];
    const float* conv_w= (const float*)d_in[10];

    const int smem_bytes = SMEM_FLOATS * sizeof(float);
    cudaFuncSetAttribute(main_kernel, cudaFuncAttributeMaxDynamicSharedMemorySize, smem_bytes);

    prep_kernel<<<BATCH + 1, 768>>>(token, ln1_w, ln1_b, lin_w, lin_b,
                                    ln2_w, ln2_b, conv_w);

    // main launched as a programmatic dependent of prep (PDL): it may begin
    // while prep runs; it calls griddepcontrol.wait before touching g_t/g_cwsum.
    cudaLaunchConfig_t cfg = {};
    cfg.gridDim  = dim3(BATCH * FSZ, 1, 1);
    cfg.blockDim = dim3(256, 1, 1);
    cfg.dynamicSmemBytes = smem_bytes;
    cudaLaunchAttribute attrs[1];
    attrs[0].id = cudaLaunchAttributeProgrammaticStreamSerialization;
    attrs[0].val.programmaticStreamSerializationAllowed = 1;
    cfg.attrs = attrs;
    cfg.numAttrs = 1;
    cudaLaunchKernelEx(&cfg, main_kernel, ori, lno_w, lno_b, conv_w, (float*)d_out);
}